// round 8
// baseline (speedup 1.0000x reference)
#include <cuda_runtime.h>
#include <cuda_bf16.h>

// Sparsemax rows of 2048 fp32 — fully warp-autonomous: one warp per row,
// zero CTA barriers. Row is read twice (second read is an L2 hit):
//   pass 1: stream row, gather candidates > THETA into per-warp smem buffer
//   solve : warp-local Michelot on candidates; tau >= THETA self-certifies
//           exactness via KKT (all discarded elements <= THETA <= tau)
//   pass 2: re-read row (L2), write max(z - tau, 0) with streaming stores
// Rare uncertified case: warp-local multi-pass Michelot over the L2 row.

#define ROWLEN  2048
#define THREADS 256
#define NWARP   (THREADS / 32)   // 8 warps per CTA
#define F4LANE  (ROWLEN / 128)   // 16 float4 per lane per row
#define CAP     64
#define THETA   2.25f
#define NEG_INF (-3.0e38f)
#define FULLM   0xffffffffu
#define OCC     8
#define GRID_CTAS (148 * OCC)

__global__ __launch_bounds__(THREADS, OCC)
void sparsemax_kernel(const float* __restrict__ z, float* __restrict__ out, int rows) {
    const int lane = threadIdx.x & 31;
    const int wid  = threadIdx.x >> 5;

    __shared__ float s_cand[NWARP][CAP];
    __shared__ int   s_n[NWARP];

    float* cand = s_cand[wid];
    int*   np   = &s_n[wid];

    const long long wstride = (long long)gridDim.x * NWARP;
    long long r = (long long)blockIdx.x * NWARP + wid;

    #pragma unroll 1
    for (; r < rows; r += wstride) {
        const float4* __restrict__ zr = reinterpret_cast<const float4*>(z + r * ROWLEN);
        float4* __restrict__       o4 = reinterpret_cast<float4*>(out + r * ROWLEN);

        if (lane == 0) *np = 0;
        __syncwarp();

        // ---- pass 1: stream row, gather candidates > THETA ----
        #pragma unroll 4
        for (int i = 0; i < F4LANE; i++) {
            float4 q = __ldg(&zr[lane + 32 * i]);
            float m4 = fmaxf(fmaxf(q.x, q.y), fmaxf(q.z, q.w));
            if (m4 > THETA) {
                if (q.x > THETA) { int ix = atomicAdd(np, 1); if (ix < CAP) cand[ix] = q.x; }
                if (q.y > THETA) { int ix = atomicAdd(np, 1); if (ix < CAP) cand[ix] = q.y; }
                if (q.z > THETA) { int ix = atomicAdd(np, 1); if (ix < CAP) cand[ix] = q.z; }
                if (q.w > THETA) { int ix = atomicAdd(np, 1); if (ix < CAP) cand[ix] = q.w; }
            }
        }
        __syncwarp();
        const int n = *np;

        // ---- warp-local Michelot on candidate set ----
        float tau;
        bool ok;
        {
            float c0 = (lane < n && lane < CAP)           ? cand[lane]      : NEG_INF;
            float c1 = (lane + 32 < n && lane + 32 < CAP) ? cand[lane + 32] : NEG_INF;
            float s0 = (c0 > NEG_INF ? c0 : 0.0f) + (c1 > NEG_INF ? c1 : 0.0f);
            #pragma unroll
            for (int o = 16; o > 0; o >>= 1) s0 += __shfl_xor_sync(FULLM, s0, o);
            int n0 = n > 0 ? (n <= CAP ? n : CAP) : 1;
            tau = (s0 - 1.0f) / (float)n0;
            int prev = -1;
            #pragma unroll 1
            for (int it = 0; it < 32; it++) {
                float s = 0.0f, cnt = 0.0f;
                bool a0 = c0 > tau, a1 = c1 > tau;
                s   += a0 ? c0 : 0.0f;    cnt += a0 ? 1.0f : 0.0f;
                s   += a1 ? c1 : 0.0f;    cnt += a1 ? 1.0f : 0.0f;
                #pragma unroll
                for (int o = 16; o > 0; o >>= 1) {
                    s   += __shfl_xor_sync(FULLM, s, o);
                    cnt += __shfl_xor_sync(FULLM, cnt, o);
                }
                if (cnt == 0.0f) break;
                tau = (s - 1.0f) / cnt;
                int k = (int)cnt;
                if (k == prev) break;
                prev = k;
            }
            ok = (n > 0 && n <= CAP && tau >= THETA);
        }

        // ---- rare fallback: warp-local multi-pass Michelot over L2 row ----
        if (!ok) {
            float s = 0.0f;
            #pragma unroll 4
            for (int i = 0; i < F4LANE; i++) {
                float4 q = __ldg(&zr[lane + 32 * i]);
                s += (q.x + q.y) + (q.z + q.w);
            }
            #pragma unroll
            for (int o = 16; o > 0; o >>= 1) s += __shfl_xor_sync(FULLM, s, o);
            tau = (s - 1.0f) * (1.0f / (float)ROWLEN);
            int k_prev = ROWLEN;
            #pragma unroll 1
            for (int it = 0; it < 64; it++) {
                float ss = 0.0f, cc = 0.0f;
                #pragma unroll 4
                for (int i = 0; i < F4LANE; i++) {
                    float4 q = __ldg(&zr[lane + 32 * i]);
                    if (q.x > tau) { ss += q.x; cc += 1.0f; }
                    if (q.y > tau) { ss += q.y; cc += 1.0f; }
                    if (q.z > tau) { ss += q.z; cc += 1.0f; }
                    if (q.w > tau) { ss += q.w; cc += 1.0f; }
                }
                #pragma unroll
                for (int o = 16; o > 0; o >>= 1) {
                    ss += __shfl_xor_sync(FULLM, ss, o);
                    cc += __shfl_xor_sync(FULLM, cc, o);
                }
                if (cc == 0.0f) break;
                tau = (ss - 1.0f) / cc;
                int k = (int)cc;
                if (k == k_prev) break;
                k_prev = k;
            }
        }

        // ---- pass 2: re-read row (L2 hit), project, streaming store ----
        #pragma unroll 4
        for (int i = 0; i < F4LANE; i++) {
            float4 q = __ldcs(&zr[lane + 32 * i]);
            float4 o;
            o.x = fmaxf(q.x - tau, 0.0f);
            o.y = fmaxf(q.y - tau, 0.0f);
            o.z = fmaxf(q.z - tau, 0.0f);
            o.w = fmaxf(q.w - tau, 0.0f);
            __stcs(&o4[lane + 32 * i], o);
        }
    }
}

extern "C" void kernel_launch(void* const* d_in, const int* in_sizes, int n_in,
                              void* d_out, int out_size) {
    const float* z = (const float*)d_in[0];
    float* out = (float*)d_out;
    int rows = in_sizes[0] / ROWLEN;
    int grid = GRID_CTAS;
    int need = (rows + NWARP - 1) / NWARP;
    if (need < grid) grid = need;
    sparsemax_kernel<<<grid, THREADS>>>(z, out, rows);
}